// round 16
// baseline (speedup 1.0000x reference)
#include <cuda_runtime.h>
#include <cuda_bf16.h>
#include <math.h>
#include <stdint.h>

#define EPS 1e-8f

#define C_CLUST 1024
#define S_SAMP  16
#define D_DIM   512
#define NROWS   (C_CLUST * S_SAMP)   // 16384

// ---- k2 tiling: 296 CTAs x 128 threads, 2 CTAs/SM ----
#define NCTA 296
#define NT 128                  // N-tile -> 8 tiles
#define KC 64
#define NTILES 8
#define NC 64                   // chunks = 8 tiles * 8
#define NTHREADS 128
#define MAXMT 4                 // max m16 units per CTA (64 rows)
#define A_CH_B   (MAXMT * 16 * 128)       // 8192 per K-chunk
#define A_BYTES  (8 * A_CH_B)             // 65536
#define B_CHUNK_B (NT * KC * 2)           // 16384
#define NBUF 2
#define SMALL_B  512
#define DYN_SMEM (SMALL_B + A_BYTES + NBUF * B_CHUNK_B + 128)  // 98944; x2 <= 227KB

// ---------------------------------------------------------------------------
__device__ __nv_bfloat16 g_Abf[NROWS * D_DIM];    // 16 MB
__device__ __nv_bfloat16 g_Bbf[C_CLUST * D_DIM];  // 1 MB
__device__ float g_invnm[C_CLUST];
__device__ float g_invnx[NROWS];
__device__ float g_sp[NROWS];

// ---------------------------------------------------------------------------
__device__ __forceinline__ uint32_t smem_u32(const void* p) {
    uint32_t a;
    asm("{ .reg .u64 t; cvta.to.shared.u64 t, %1; cvt.u32.u64 %0, t; }" : "=r"(a) : "l"(p));
    return a;
}
__device__ __forceinline__ void cp_async16(uint32_t dst, const void* src) {
    asm volatile("cp.async.cg.shared.global [%0], [%1], 16;\n" :: "r"(dst), "l"(src) : "memory");
}
__device__ __forceinline__ void cp_commit() {
    asm volatile("cp.async.commit_group;\n" ::: "memory");
}
template <int N> __device__ __forceinline__ void cp_wait() {
    asm volatile("cp.async.wait_group %0;\n" :: "n"(N) : "memory");
}
__device__ __forceinline__ void ldsm4(uint32_t* r, uint32_t addr) {
    asm volatile("ldmatrix.sync.aligned.m8n8.x4.shared.b16 {%0,%1,%2,%3}, [%4];"
                 : "=r"(r[0]), "=r"(r[1]), "=r"(r[2]), "=r"(r[3]) : "r"(addr));
}
__device__ __forceinline__ void mma16816(float* c, const uint32_t* a, uint32_t b0, uint32_t b1) {
    asm volatile("mma.sync.aligned.m16n8k16.row.col.f32.bf16.bf16.f32 "
                 "{%0,%1,%2,%3}, {%4,%5,%6,%7}, {%8,%9}, {%0,%1,%2,%3};"
                 : "+f"(c[0]), "+f"(c[1]), "+f"(c[2]), "+f"(c[3])
                 : "r"(a[0]), "r"(a[1]), "r"(a[2]), "r"(a[3]), "r"(b0), "r"(b1));
}
__device__ __forceinline__ uint32_t sw_addr(uint32_t base, int row, int kseg) {
    return base + (uint32_t)(row << 7) + (uint32_t)(((kseg ^ (row & 7)) & 7) << 4);
}

// ---------------------------------------------------------------------------
// Kernel 1 (round-12 version): per-cluster stats + bf16 conversion.
// ---------------------------------------------------------------------------
__global__ void __launch_bounds__(256) k1_stats(const float* __restrict__ x,
                                                float* __restrict__ out)
{
    __shared__ float xs[S_SAMP * D_DIM];   // 32 KB
    __shared__ float ssum[D_DIM];
    __shared__ float sred[8];
    __shared__ float s_sumsq;

    const int j   = blockIdx.x;
    const int tid = threadIdx.x;

    if (j == 0 && tid == 0) out[0] = 0.f;   // k2 accumulates into out

    const float4* gx = (const float4*)(x + (size_t)j * S_SAMP * D_DIM);
    float4* xs4 = (float4*)xs;
    #pragma unroll
    for (int it = 0; it < 8; it++) {
        const int i4 = tid + it * 256;
        const float4 v = gx[i4];
        xs4[i4] = v;
        unsigned short h0 = __bfloat16_as_ushort(__float2bfloat16(v.x));
        unsigned short h1 = __bfloat16_as_ushort(__float2bfloat16(v.y));
        unsigned short h2 = __bfloat16_as_ushort(__float2bfloat16(v.z));
        unsigned short h3 = __bfloat16_as_ushort(__float2bfloat16(v.w));
        ((uint2*)g_Abf)[(size_t)j * 2048 + i4] =
            make_uint2(((uint32_t)h1 << 16) | h0, ((uint32_t)h3 << 16) | h2);
    }
    __syncthreads();

    const int d0 = tid, d1 = tid + 256;
    float s0 = 0.f, s1 = 0.f;
    #pragma unroll
    for (int i = 0; i < S_SAMP; i++) {
        s0 += xs[i * D_DIM + d0];
        s1 += xs[i * D_DIM + d1];
    }
    ssum[d0] = s0;
    ssum[d1] = s1;
    g_Bbf[(size_t)j * D_DIM + d0] = __float2bfloat16(s0 * (1.f / 16.f));
    g_Bbf[(size_t)j * D_DIM + d1] = __float2bfloat16(s1 * (1.f / 16.f));

    float p = s0 * s0 + s1 * s1;
    #pragma unroll
    for (int off = 16; off; off >>= 1) p += __shfl_down_sync(0xffffffffu, p, off);
    if ((tid & 31) == 0) sred[tid >> 5] = p;
    __syncthreads();
    if (tid == 0) {
        float t = 0.f;
        #pragma unroll
        for (int wi = 0; wi < 8; wi++) t += sred[wi];
        s_sumsq = t;
        g_invnm[j] = 16.f / sqrtf(t);
    }
    __syncthreads();
    const float sumsq = s_sumsq;

    const int w = tid >> 5, l = tid & 31;
    #pragma unroll
    for (int rr = 0; rr < 2; rr++) {
        const int i = w + rr * 8;
        float nx2 = 0.f, dt = 0.f;
        #pragma unroll
        for (int c = 0; c < 16; c++) {
            const int d = l + c * 32;
            const float a = xs[i * D_DIM + d];
            nx2 += a * a;
            dt  += a * ssum[d];
        }
        #pragma unroll
        for (int off = 16; off; off >>= 1) {
            nx2 += __shfl_down_sync(0xffffffffu, nx2, off);
            dt  += __shfl_down_sync(0xffffffffu, dt,  off);
        }
        if (l == 0) {
            const float loo_dot = (dt - nx2) * (1.f / 15.f);
            const float nloo2   = fmaxf((sumsq - 2.f * dt + nx2) * (1.f / 225.f), 0.f);
            const float nx      = sqrtf(nx2);
            g_invnx[j * S_SAMP + i] = 1.f / nx;
            g_sp[j * S_SAMP + i]    = loo_dot / fmaxf(nx * sqrtf(nloo2), EPS);
        }
    }
}

// ---------------------------------------------------------------------------
// Kernel 2: 296 CTAs x 128 threads (4 warps), 2 CTAs/SM.
// CTA c units: c<136 -> 4 (s16=4c); 136..147 -> 3 (s16=544+3(c-136));
//              >=148 -> 3 (s16=580+3(c-148)).  Pairs (b, b+148) sum to <=7.
// Warp wn owns cols [wn*32,+32) of each 128-wide N-tile; warp-private B ring
// (2 slots), zero cross-warp sync in the main loop.
// ---------------------------------------------------------------------------
__global__ void __launch_bounds__(NTHREADS, 2) k2_gemm_lse(const float* __restrict__ wptr,
                                                           float* __restrict__ out)
{
    extern __shared__ char rawsm[];
    char* smbase = (char*)(((uintptr_t)rawsm + 127u) & ~(uintptr_t)127u);

    float* s_invnx = (float*)smbase;          // 64 floats
    float* s_sp    = s_invnx + 64;            // 64 floats
    char*  smA_p   = smbase + SMALL_B;
    const uint32_t smA = smem_u32(smA_p);
    const uint32_t smB = smA + A_BYTES;
    float* s_red     = (float*)(smA_p + A_BYTES);   // aliases B ring: 4*64
    float* s_rowloss = s_red + 4 * 64;              // 64
    float* s_part    = s_rowloss + 64;              // 4

    const int tid  = threadIdx.x;
    const int lane = tid & 31;
    const int wn   = tid >> 5;          // warp 0..3 = column-slice owner
    const int lq   = lane >> 3, l7 = lane & 7;

    const int c = blockIdx.x;
    int s16, nmt;
    if (c < 136)      { nmt = 4; s16 = c * 4; }
    else if (c < 148) { nmt = 3; s16 = 544 + (c - 136) * 3; }
    else              { nmt = 3; s16 = 580 + (c - 148) * 3; }
    const int nr = nmt * 16;

    if (tid < nr) {
        s_invnx[tid] = g_invnx[s16 * 16 + tid];
        s_sp[tid]    = g_sp[s16 * 16 + tid];
    }

    // ---- A prologue: nr rows x 512 cols (8 chunks), one cp.async group ----
    const __nv_bfloat16* Asrc = g_Abf + (size_t)s16 * 16 * D_DIM;
    #pragma unroll 1
    for (int kc = 0; kc < 8; kc++) {
        for (int i = tid; i < nr * 8; i += NTHREADS) {
            const int r = i >> 3, s = i & 7;
            cp_async16(smA + (uint32_t)kc * A_CH_B + (uint32_t)(r << 7) +
                           (uint32_t)(((s ^ (r & 7)) & 7) << 4),
                       Asrc + (size_t)r * D_DIM + kc * KC + s * 8);
        }
    }
    cp_commit();

    // ---- warp-private B chunk loader: 32 rows x 8 segs of slot gg&1 ----
    auto load_B = [&](int gg) {
        const uint32_t slot = smB + (uint32_t)(gg & 1) * B_CHUNK_B;
        const __nv_bfloat16* bsrc =
            g_Bbf + (size_t)((gg >> 3) * NT + wn * 32) * D_DIM + (gg & 7) * KC;
        #pragma unroll
        for (int it = 0; it < 8; it++) {
            const int i = lane + it * 32;        // 0..255
            const int r = i >> 3, s = i & 7;     // r 0..31
            const int row = wn * 32 + r;
            cp_async16(slot + (uint32_t)(row << 7) +
                           (uint32_t)(((s ^ (row & 7)) & 7) << 4),
                       bsrc + (size_t)r * D_DIM + s * 8);
        }
        cp_commit();
    };

    load_B(0);
    load_B(1);

    const float wp = log1pf(expf(wptr[0]));

    float acc[MAXMT][4][4];   // 64 regs
    #pragma unroll
    for (int mt = 0; mt < MAXMT; mt++)
        #pragma unroll
        for (int p = 0; p < 4; p++)
            #pragma unroll
            for (int e = 0; e < 4; e++) acc[mt][p][e] = 0.f;

    float es[MAXMT][2];
    #pragma unroll
    for (int mt = 0; mt < MAXMT; mt++) { es[mt][0] = 0.f; es[mt][1] = 0.f; }

    auto mma_chunk = [&](int kcA, int slot) {
        const uint32_t Ac = smA + (uint32_t)kcA * A_CH_B;
        const uint32_t Bs = smB + (uint32_t)slot * B_CHUNK_B;
        #pragma unroll
        for (int k16 = 0; k16 < 4; k16++) {
            uint32_t a[MAXMT][4];
            #pragma unroll
            for (int mt = 0; mt < MAXMT; mt++)
                if (mt < nmt)
                    ldsm4(a[mt], sw_addr(Ac, mt * 16 + (lq & 1) * 8 + l7,
                                         k16 * 2 + (lq >> 1)));
            uint32_t b[2][4];
            #pragma unroll
            for (int p2 = 0; p2 < 2; p2++)
                ldsm4(b[p2], sw_addr(Bs, wn * 32 + p2 * 16 + (lq >> 1) * 8 + l7,
                                     k16 * 2 + (lq & 1)));
            #pragma unroll
            for (int p2 = 0; p2 < 2; p2++)
                #pragma unroll
                for (int mt = 0; mt < MAXMT; mt++)
                    if (mt < nmt) {
                        mma16816(acc[mt][p2 * 2],     a[mt], b[p2][0], b[p2][1]);
                        mma16816(acc[mt][p2 * 2 + 1], a[mt], b[p2][2], b[p2][3]);
                    }
        }
    };

    auto epi_tile = [&](int t) {
        #pragma unroll
        for (int p = 0; p < 4; p++) {
            const int c0  = t * NT + wn * 32 + p * 8 + (lane & 3) * 2;
            const float nm0 = __ldg(&g_invnm[c0]);
            const float nm1 = __ldg(&g_invnm[c0 + 1]);
            #pragma unroll
            for (int mt = 0; mt < MAXMT; mt++) {
                if (mt >= nmt) break;
                const int jr = s16 + mt;
                #pragma unroll
                for (int h = 0; h < 2; h++) {
                    const int rl = mt * 16 + h * 8 + (lane >> 2);
                    const float inx = s_invnx[rl];
                    float v0 = acc[mt][p][h * 2 + 0] * inx * nm0;
                    float v1 = acc[mt][p][h * 2 + 1] * inx * nm1;
                    if (c0     == jr) v0 = s_sp[rl];
                    if (c0 + 1 == jr) v1 = s_sp[rl];
                    es[mt][h] += __expf(wp * v0) + __expf(wp * v1);
                    acc[mt][p][h * 2 + 0] = 0.f;
                    acc[mt][p][h * 2 + 1] = 0.f;
                }
            }
        }
    };

    // ---- main loop: warp-private pipeline, loads issued after consumption ----
    #pragma unroll 1
    for (int t = 0; t < NTILES; t++) {
        #pragma unroll
        for (int kc = 0; kc < 8; kc++) {
            const int g = t * 8 + kc;
            if (g < NC - 1) cp_wait<1>(); else cp_wait<0>();
            if (g == 0) __syncthreads();   // A (cooperative) + s_invnx/s_sp ready
            else        __syncwarp();
            mma_chunk(kc, g & 1);
            if (g + 2 < NC) load_B(g + 2); // slot g&1 free: this warp just read it
        }
        epi_tile(t);
    }

    __syncthreads();   // all warps done; safe to alias B ring with s_red

    #pragma unroll
    for (int mt = 0; mt < MAXMT; mt++) {
        if (mt >= nmt) break;
        #pragma unroll
        for (int h = 0; h < 2; h++) {
            float v = es[mt][h];
            v += __shfl_xor_sync(0xffffffffu, v, 1);
            v += __shfl_xor_sync(0xffffffffu, v, 2);
            if ((lane & 3) == 0)
                s_red[wn * 64 + mt * 16 + h * 8 + (lane >> 2)] = v;
        }
    }
    __syncthreads();
    if (tid < nr) {
        float tot = 0.f;
        #pragma unroll
        for (int w = 0; w < 4; w++) tot += s_red[w * 64 + tid];
        s_rowloss[tid] = logf(tot) - wp * s_sp[tid];
    }
    __syncthreads();
    {
        float v = (tid < nr) ? s_rowloss[tid] : 0.f;
        #pragma unroll
        for (int off = 16; off; off >>= 1) v += __shfl_down_sync(0xffffffffu, v, off);
        if (lane == 0) s_part[wn] = v;
    }
    __syncthreads();
    if (tid == 0) {
        float t = 0.f;
        #pragma unroll
        for (int i = 0; i < 4; i++) t += s_part[i];
        atomicAdd(out, t * (1.f / (float)NROWS));
    }
}

extern "C" void kernel_launch(void* const* d_in, const int* in_sizes, int n_in,
                              void* d_out, int out_size)
{
    const float* x = (const float*)d_in[0];
    const float* w = (const float*)d_in[1];
    // b cancels: lse(wp*sim + b) - (wp*sim_pos + b) is b-independent.
    float* out = (float*)d_out;

    cudaFuncSetAttribute(k2_gemm_lse, cudaFuncAttributeMaxDynamicSharedMemorySize, DYN_SMEM);

    k1_stats<<<C_CLUST, 256>>>(x, out);
    k2_gemm_lse<<<NCTA, NTHREADS, DYN_SMEM>>>(w, out);
}

// round 17
// speedup vs baseline: 1.0326x; 1.0326x over previous
#include <cuda_runtime.h>
#include <cuda_bf16.h>
#include <math.h>
#include <stdint.h>

#define EPS 1e-8f

#define C_CLUST 1024
#define S_SAMP  16
#define D_DIM   512
#define NROWS   (C_CLUST * S_SAMP)   // 16384

// ---- k2 tiling (round-12 structure + per-warp tile phase) ----
#define NCTA 148
#define NT 256
#define KC 64
#define NTILES 4
#define NC 32
#define NTHREADS 256
#define MAXMT 7
#define A_CH_B   (MAXMT * 16 * 128)       // 14336
#define A_BYTES  (8 * A_CH_B)             // 114688
#define B_CHUNK_B (NT * KC * 2)           // 32768
#define NBUF 3
#define SMALL_B  1024
#define DYN_SMEM (SMALL_B + A_BYTES + NBUF * B_CHUNK_B + 256)  // 214272

// ---------------------------------------------------------------------------
__device__ __nv_bfloat16 g_Abf[NROWS * D_DIM];    // 16 MB
__device__ __nv_bfloat16 g_Bbf[C_CLUST * D_DIM];  // 1 MB
__device__ float g_invnm[C_CLUST];
__device__ float g_invnx[NROWS];
__device__ float g_sp[NROWS];

// ---------------------------------------------------------------------------
__device__ __forceinline__ uint32_t smem_u32(const void* p) {
    uint32_t a;
    asm("{ .reg .u64 t; cvta.to.shared.u64 t, %1; cvt.u32.u64 %0, t; }" : "=r"(a) : "l"(p));
    return a;
}
__device__ __forceinline__ void cp_async16(uint32_t dst, const void* src) {
    asm volatile("cp.async.cg.shared.global [%0], [%1], 16;\n" :: "r"(dst), "l"(src) : "memory");
}
__device__ __forceinline__ void cp_commit() {
    asm volatile("cp.async.commit_group;\n" ::: "memory");
}
template <int N> __device__ __forceinline__ void cp_wait() {
    asm volatile("cp.async.wait_group %0;\n" :: "n"(N) : "memory");
}
__device__ __forceinline__ void ldsm4(uint32_t* r, uint32_t addr) {
    asm volatile("ldmatrix.sync.aligned.m8n8.x4.shared.b16 {%0,%1,%2,%3}, [%4];"
                 : "=r"(r[0]), "=r"(r[1]), "=r"(r[2]), "=r"(r[3]) : "r"(addr));
}
__device__ __forceinline__ void mma16816(float* c, const uint32_t* a, uint32_t b0, uint32_t b1) {
    asm volatile("mma.sync.aligned.m16n8k16.row.col.f32.bf16.bf16.f32 "
                 "{%0,%1,%2,%3}, {%4,%5,%6,%7}, {%8,%9}, {%0,%1,%2,%3};"
                 : "+f"(c[0]), "+f"(c[1]), "+f"(c[2]), "+f"(c[3])
                 : "r"(a[0]), "r"(a[1]), "r"(a[2]), "r"(a[3]), "r"(b0), "r"(b1));
}
__device__ __forceinline__ uint32_t sw_addr(uint32_t base, int row, int kseg) {
    return base + (uint32_t)(row << 7) + (uint32_t)(((kseg ^ (row & 7)) & 7) << 4);
}

// ---------------------------------------------------------------------------
// Kernel 1 (round-12 version): per-cluster stats + bf16 conversion.
// ---------------------------------------------------------------------------
__global__ void __launch_bounds__(256) k1_stats(const float* __restrict__ x,
                                                float* __restrict__ out)
{
    __shared__ float xs[S_SAMP * D_DIM];   // 32 KB
    __shared__ float ssum[D_DIM];
    __shared__ float sred[8];
    __shared__ float s_sumsq;

    const int j   = blockIdx.x;
    const int tid = threadIdx.x;

    if (j == 0 && tid == 0) out[0] = 0.f;   // k2 accumulates into out

    const float4* gx = (const float4*)(x + (size_t)j * S_SAMP * D_DIM);
    float4* xs4 = (float4*)xs;
    #pragma unroll
    for (int it = 0; it < 8; it++) {
        const int i4 = tid + it * 256;
        const float4 v = gx[i4];
        xs4[i4] = v;
        unsigned short h0 = __bfloat16_as_ushort(__float2bfloat16(v.x));
        unsigned short h1 = __bfloat16_as_ushort(__float2bfloat16(v.y));
        unsigned short h2 = __bfloat16_as_ushort(__float2bfloat16(v.z));
        unsigned short h3 = __bfloat16_as_ushort(__float2bfloat16(v.w));
        ((uint2*)g_Abf)[(size_t)j * 2048 + i4] =
            make_uint2(((uint32_t)h1 << 16) | h0, ((uint32_t)h3 << 16) | h2);
    }
    __syncthreads();

    const int d0 = tid, d1 = tid + 256;
    float s0 = 0.f, s1 = 0.f;
    #pragma unroll
    for (int i = 0; i < S_SAMP; i++) {
        s0 += xs[i * D_DIM + d0];
        s1 += xs[i * D_DIM + d1];
    }
    ssum[d0] = s0;
    ssum[d1] = s1;
    g_Bbf[(size_t)j * D_DIM + d0] = __float2bfloat16(s0 * (1.f / 16.f));
    g_Bbf[(size_t)j * D_DIM + d1] = __float2bfloat16(s1 * (1.f / 16.f));

    float p = s0 * s0 + s1 * s1;
    #pragma unroll
    for (int off = 16; off; off >>= 1) p += __shfl_down_sync(0xffffffffu, p, off);
    if ((tid & 31) == 0) sred[tid >> 5] = p;
    __syncthreads();
    if (tid == 0) {
        float t = 0.f;
        #pragma unroll
        for (int wi = 0; wi < 8; wi++) t += sred[wi];
        s_sumsq = t;
        g_invnm[j] = 16.f / sqrtf(t);
    }
    __syncthreads();
    const float sumsq = s_sumsq;

    const int w = tid >> 5, l = tid & 31;
    #pragma unroll
    for (int rr = 0; rr < 2; rr++) {
        const int i = w + rr * 8;
        float nx2 = 0.f, dt = 0.f;
        #pragma unroll
        for (int c = 0; c < 16; c++) {
            const int d = l + c * 32;
            const float a = xs[i * D_DIM + d];
            nx2 += a * a;
            dt  += a * ssum[d];
        }
        #pragma unroll
        for (int off = 16; off; off >>= 1) {
            nx2 += __shfl_down_sync(0xffffffffu, nx2, off);
            dt  += __shfl_down_sync(0xffffffffu, dt,  off);
        }
        if (l == 0) {
            const float loo_dot = (dt - nx2) * (1.f / 15.f);
            const float nloo2   = fmaxf((sumsq - 2.f * dt + nx2) * (1.f / 225.f), 0.f);
            const float nx      = sqrtf(nx2);
            g_invnx[j * S_SAMP + i] = 1.f / nx;
            g_sp[j * S_SAMP + i]    = loo_dot / fmaxf(nx * sqrtf(nloo2), EPS);
        }
    }
}

// ---------------------------------------------------------------------------
// Kernel 2: bf16 mma.sync GEMM + fused logsumexp.
// 148 CTAs x 256 threads. Warp wn owns output cols [wn*32,+32) of every
// N-tile AND its private 32-row slice of every B ring slot -> each warp runs
// a fully private pipeline and processes N-tiles in its OWN order:
//   t = (tt + toff) & 3,  toff = ((wn & 3) + 2*(wn >> 2)) & 3
// so the two warps sharing an SMSP are 2 tiles out of phase: one warp's
// epilogue (MUFU burst) overlaps the other's HMMA stream.
// ---------------------------------------------------------------------------
__global__ void __launch_bounds__(NTHREADS, 1) k2_gemm_lse(const float* __restrict__ wptr,
                                                           float* __restrict__ out)
{
    extern __shared__ char rawsm[];
    char* smbase = (char*)(((uintptr_t)rawsm + 127u) & ~(uintptr_t)127u);

    float* s_invnx = (float*)smbase;
    float* s_sp    = s_invnx + 112;
    char*  smA_p   = smbase + SMALL_B;
    const uint32_t smA = smem_u32(smA_p);
    const uint32_t smB = smA + A_BYTES;
    float* s_red     = (float*)(smA_p + A_BYTES);   // aliases B ring
    float* s_rowloss = s_red + 8 * 112;
    float* s_part    = s_rowloss + 112;

    const int tid  = threadIdx.x;
    const int lane = tid & 31;
    const int wn   = tid >> 5;
    const int lq   = lane >> 3, l7 = lane & 7;
    const int toff = ((wn & 3) + 2 * (wn >> 2)) & 3;   // SMSP partners differ by 2

    const int c    = blockIdx.x;
    const int s16  = (c < 136) ? c * 7 : 952 + (c - 136) * 6;
    const int nmt  = (c < 136) ? 7 : 6;
    const int nr   = nmt * 16;

    if (tid < nr) {
        s_invnx[tid] = g_invnx[s16 * 16 + tid];
        s_sp[tid]    = g_sp[s16 * 16 + tid];
    }

    // ---- A prologue: one cp.async group (cooperative) ----
    const __nv_bfloat16* Asrc = g_Abf + (size_t)s16 * 16 * D_DIM;
    #pragma unroll 1
    for (int kc = 0; kc < 8; kc++) {
        for (int i = tid; i < nr * 8; i += NTHREADS) {
            const int r = i >> 3, s = i & 7;
            cp_async16(smA + (uint32_t)kc * A_CH_B + (uint32_t)(r << 7) +
                           (uint32_t)(((s ^ (r & 7)) & 7) << 4),
                       Asrc + (size_t)r * D_DIM + kc * KC + s * 8);
        }
    }
    cp_commit();

    // ---- warp-private B loader by PIPELINE POSITION p ----
    // position p -> tile (p/8 + toff)&3, k-chunk p&7, ring slot p%NBUF
    auto load_B_pos = [&](int p) {
        const int nt  = ((p >> 3) + toff) & 3;
        const int kc  = p & 7;
        const uint32_t slot = smB + (uint32_t)(p % NBUF) * B_CHUNK_B;
        const __nv_bfloat16* bsrc =
            g_Bbf + (size_t)(nt * NT + wn * 32) * D_DIM + kc * KC;
        #pragma unroll
        for (int it = 0; it < 8; it++) {
            const int i = lane + it * 32;
            const int r = i >> 3, s = i & 7;
            const int row = wn * 32 + r;
            cp_async16(slot + (uint32_t)(row << 7) +
                           (uint32_t)(((s ^ (row & 7)) & 7) << 4),
                       bsrc + (size_t)r * D_DIM + s * 8);
        }
        cp_commit();
    };

    load_B_pos(0);
    load_B_pos(1);

    const float wp = log1pf(expf(wptr[0]));

    cp_wait<1>();      // A + B(pos 0) complete; B(pos 1) may be in flight
    __syncthreads();   // A + s_invnx/s_sp visible to all

    float acc[MAXMT][4][4];
    #pragma unroll
    for (int mt = 0; mt < MAXMT; mt++)
        #pragma unroll
        for (int p = 0; p < 4; p++)
            #pragma unroll
            for (int e = 0; e < 4; e++) acc[mt][p][e] = 0.f;

    float es[MAXMT][2];
    #pragma unroll
    for (int mt = 0; mt < MAXMT; mt++) { es[mt][0] = 0.f; es[mt][1] = 0.f; }

    auto mma_chunk = [&](int kcA, int slot) {
        const uint32_t Ac = smA + (uint32_t)kcA * A_CH_B;
        const uint32_t Bs = smB + (uint32_t)slot * B_CHUNK_B;
        #pragma unroll
        for (int k16 = 0; k16 < 4; k16++) {
            uint32_t a[MAXMT][4];
            #pragma unroll
            for (int mt = 0; mt < MAXMT; mt++)
                if (mt < nmt)
                    ldsm4(a[mt], sw_addr(Ac, mt * 16 + (lq & 1) * 8 + l7,
                                         k16 * 2 + (lq >> 1)));
            uint32_t b[2][4];
            #pragma unroll
            for (int p2 = 0; p2 < 2; p2++)
                ldsm4(b[p2], sw_addr(Bs, wn * 32 + p2 * 16 + (lq >> 1) * 8 + l7,
                                     k16 * 2 + (lq & 1)));
            #pragma unroll
            for (int p2 = 0; p2 < 2; p2++)
                #pragma unroll
                for (int mt = 0; mt < MAXMT; mt++)
                    if (mt < nmt) {
                        mma16816(acc[mt][p2 * 2],     a[mt], b[p2][0], b[p2][1]);
                        mma16816(acc[mt][p2 * 2 + 1], a[mt], b[p2][2], b[p2][3]);
                    }
        }
    };

    auto epi_tile = [&](int t) {
        #pragma unroll
        for (int p = 0; p < 4; p++) {
            const int c0  = t * NT + wn * 32 + p * 8 + (lane & 3) * 2;
            const float nm0 = __ldg(&g_invnm[c0]);
            const float nm1 = __ldg(&g_invnm[c0 + 1]);
            #pragma unroll
            for (int mt = 0; mt < MAXMT; mt++) {
                if (mt >= nmt) break;
                const int jr = s16 + mt;
                #pragma unroll
                for (int h = 0; h < 2; h++) {
                    const int rl = mt * 16 + h * 8 + (lane >> 2);
                    const float inx = s_invnx[rl];
                    float v0 = acc[mt][p][h * 2 + 0] * inx * nm0;
                    float v1 = acc[mt][p][h * 2 + 1] * inx * nm1;
                    if (c0     == jr) v0 = s_sp[rl];
                    if (c0 + 1 == jr) v1 = s_sp[rl];
                    es[mt][h] += __expf(wp * v0) + __expf(wp * v1);
                    acc[mt][p][h * 2 + 0] = 0.f;
                    acc[mt][p][h * 2 + 1] = 0.f;
                }
            }
        }
    };

    // ---- main loop: warp-private pipeline, per-warp tile order ----
    #pragma unroll 1
    for (int tt = 0; tt < NTILES; tt++) {
        const int t = (tt + toff) & 3;   // this warp's actual tile
        #pragma unroll
        for (int kc = 0; kc < 8; kc++) {
            const int p = tt * 8 + kc;   // pipeline position
            if (p > 0) {
                if (p < NC - 1) cp_wait<1>(); else cp_wait<0>();
                __syncwarp();
            }
            if (p + 2 < NC) load_B_pos(p + 2);
            mma_chunk(kc, p % NBUF);
        }
        epi_tile(t);
    }

    __syncthreads();   // all warps done; safe to alias B ring with s_red

    #pragma unroll
    for (int mt = 0; mt < MAXMT; mt++) {
        if (mt >= nmt) break;
        #pragma unroll
        for (int h = 0; h < 2; h++) {
            float v = es[mt][h];
            v += __shfl_xor_sync(0xffffffffu, v, 1);
            v += __shfl_xor_sync(0xffffffffu, v, 2);
            if ((lane & 3) == 0)
                s_red[wn * 112 + mt * 16 + h * 8 + (lane >> 2)] = v;
        }
    }
    __syncthreads();
    if (tid < nr) {
        float tot = 0.f;
        #pragma unroll
        for (int w = 0; w < 8; w++) tot += s_red[w * 112 + tid];
        s_rowloss[tid] = logf(tot) - wp * s_sp[tid];
    }
    __syncthreads();
    {
        float v = (tid < nr) ? s_rowloss[tid] : 0.f;
        #pragma unroll
        for (int off = 16; off; off >>= 1) v += __shfl_down_sync(0xffffffffu, v, off);
        if (lane == 0) s_part[wn] = v;
    }
    __syncthreads();
    if (tid == 0) {
        float t = 0.f;
        #pragma unroll
        for (int i = 0; i < 8; i++) t += s_part[i];
        atomicAdd(out, t * (1.f / (float)NROWS));
    }
}

extern "C" void kernel_launch(void* const* d_in, const int* in_sizes, int n_in,
                              void* d_out, int out_size)
{
    const float* x = (const float*)d_in[0];
    const float* w = (const float*)d_in[1];
    // b cancels: lse(wp*sim + b) - (wp*sim_pos + b) is b-independent.
    float* out = (float*)d_out;

    cudaFuncSetAttribute(k2_gemm_lse, cudaFuncAttributeMaxDynamicSharedMemorySize, DYN_SMEM);

    k1_stats<<<C_CLUST, 256>>>(x, out);
    k2_gemm_lse<<<NCTA, NTHREADS, DYN_SMEM>>>(w, out);
}